// round 8
// baseline (speedup 1.0000x reference)
#include <cuda_runtime.h>
#include <cuda_fp16.h>
#include <math.h>
#include <stdint.h>

// ---------------------------------------------------------------- constants
#define N_TOK 16384
#define NE    4096
#define ED    64
#define BM    128          // tokens per CTA
#define BN    128          // codes per chunk
#define NCH   (NE/BN)      // 32
#define NBLK  (N_TOK/BM)   // 128
#define NTHR  512
#define EPSW  5.0e-5f      // d-grid ties (1.5e-5) + A-rounding (7.6e-6) + 2*mma err + slack

#define OUT_ZQ_OFF   1
#define OUT_IDX_OFF  (1 + (size_t)N_TOK*ED)
#define OUT_PERP_OFF (OUT_IDX_OFF + N_TOK)

// SMEM layout of vq_main
#define OFF_A    0                 // zh 16K + zl 16K
#define OFF_B    32768             // 2 bufs x 16K (eh only)
#define OFF_SES  65536             // 16K fp32 ||e||^2
#define SMEM_MAIN (OFF_SES + NE*4) // 81920

// ---------------------------------------------------------------- scratch
__device__ __align__(16) __half d_zh[N_TOK*ED];   // hi(-2z)
__device__ __align__(16) __half d_zl[N_TOK*ED];   // lo(-2z)
__device__ __align__(16) __half d_eh[NE*ED];      // hi(e)
__device__ float d_sz[N_TOK];
__device__ float d_se[NE];
__device__ int   d_counts[NE];
__device__ float d_losstok[N_TOK];
__device__ float d_c2v[(size_t)N_TOK*4];          // best-2 per (token, half)
__device__ int   d_c2i[(size_t)N_TOK*4];
__device__ int   d_win[N_TOK];
__device__ int   d_flag[N_TOK];
__device__ int   d_nflag;

// ---------------------------------------------------------------- utils
static __device__ __forceinline__ uint32_t smem_u32(const void* p) {
    uint32_t a;
    asm("{ .reg .u64 t; cvta.to.shared.u64 t, %1; cvt.u32.u64 %0, t; }"
        : "=r"(a) : "l"(p));
    return a;
}
static __device__ __forceinline__ uint32_t swz(uint32_t o) { return o ^ ((o >> 3) & 0x70); }

static __device__ __forceinline__ void ldsm4(uint32_t& r0, uint32_t& r1,
                                             uint32_t& r2, uint32_t& r3, uint32_t a) {
    asm volatile("ldmatrix.sync.aligned.m8n8.x4.shared.b16 {%0,%1,%2,%3}, [%4];"
                 : "=r"(r0), "=r"(r1), "=r"(r2), "=r"(r3) : "r"(a));
}
static __device__ __forceinline__ void mma_f16(float c[4], const uint32_t a[4],
                                               uint32_t b0, uint32_t b1) {
    asm volatile("mma.sync.aligned.m16n8k16.row.col.f32.f16.f16.f32 "
                 "{%0,%1,%2,%3}, {%4,%5,%6,%7}, {%8,%9}, {%0,%1,%2,%3};"
                 : "+f"(c[0]), "+f"(c[1]), "+f"(c[2]), "+f"(c[3])
                 : "r"(a[0]), "r"(a[1]), "r"(a[2]), "r"(a[3]), "r"(b0), "r"(b1));
}
#define CP_ASYNC16(s, g) \
    asm volatile("cp.async.cg.shared.global [%0], [%1], 16;" :: "r"(s), "l"(g))
#define CP_COMMIT() asm volatile("cp.async.commit_group;" ::: "memory")
#define CP_WAIT(n)  asm volatile("cp.async.wait_group %0;" :: "n"(n) : "memory")

// branchless best-2; strict < + increasing-k order keeps first index on ties
#define UPD2(v0, i0, v1, i1, dv, kk) do { \
    bool _p0 = (dv) < (v0); \
    bool _p1 = (dv) < (v1); \
    (v1) = _p0 ? (v0) : (_p1 ? (dv) : (v1)); \
    (i1) = _p0 ? (i0) : (_p1 ? (kk) : (i1)); \
    (v0) = _p0 ? (dv) : (v0); \
    (i0) = _p0 ? (kk) : (i0); \
} while (0)

// merge two best-2 sets (values+indices), index tie-break
#define MERGE2(v0, i0, v1, i1, w0, j0, w1, j1) do { \
    bool _t = ((w0) < (v0)) || ((w0) == (v0) && (j0) < (i0)); \
    float _nv0 = _t ? (w0) : (v0); int _ni0 = _t ? (j0) : (i0); \
    float _c1v = _t ? (v0) : (w0); int _c1i = _t ? (i0) : (j0); \
    float _c2v = _t ? (w1) : (v1); int _c2i = _t ? (j1) : (i1); \
    bool _s = (_c1v < _c2v) || (_c1v == _c2v && _c1i < _c2i); \
    (v1) = _s ? _c1v : _c2v; (i1) = _s ? _c1i : _c2i; \
    (v0) = _nv0; (i0) = _ni0; \
} while (0)

// exact reference-chain distance (bit-matched vs reference in R1/R7)
static __device__ __forceinline__ float exact_d(const float* __restrict__ zr,
                                                const float* __restrict__ cb,
                                                float szt, int ic) {
    const float4* c4 = (const float4*)(cb + (size_t)ic * ED);
    float dot = 0.f;
    #pragma unroll
    for (int q = 0; q < 16; q++) {
        float4 cv = c4[q];
        dot = __fmaf_rn(zr[q * 4 + 0], cv.x, dot);
        dot = __fmaf_rn(zr[q * 4 + 1], cv.y, dot);
        dot = __fmaf_rn(zr[q * 4 + 2], cv.z, dot);
        dot = __fmaf_rn(zr[q * 4 + 3], cv.w, dot);
    }
    return __fmaf_rn(-2.0f, dot, __fadd_rn(szt, d_se[ic]));
}

// ---------------------------------------------------------------- L1: prep
__global__ void __launch_bounds__(256) vq_prep(const float* __restrict__ z,
                                               const float* __restrict__ cb) {
    int b = blockIdx.x, tid = threadIdx.x;
    int w = tid >> 5, lane = tid & 31;
    int row = b * 8 + w;
    bool isz = row < N_TOK;
    const float* src = isz ? z : cb;
    int r = isz ? row : row - N_TOK;

    float2 v = *(const float2*)&src[(size_t)r * ED + lane * 2];
    float sc = isz ? -2.0f : 1.0f;
    float m0 = sc * v.x, m1 = sc * v.y;
    __half h0 = __float2half_rn(m0), h1 = __float2half_rn(m1);
    __half2 hh; hh.x = h0; hh.y = h1;
    if (isz) {
        float l0 = m0 - __half2float(h0), l1 = m1 - __half2float(h1);
        __half2 ll; ll.x = __float2half_rn(l0); ll.y = __float2half_rn(l1);
        ((__half2*)d_zh)[(size_t)r * 32 + lane] = hh;
        ((__half2*)d_zl)[(size_t)r * 32 + lane] = ll;
    } else {
        ((__half2*)d_eh)[(size_t)r * 32 + lane] = hh;
    }

    float s = __fmaf_rn(v.x, v.x, v.y * v.y);
    #pragma unroll
    for (int o = 16; o; o >>= 1) s += __shfl_xor_sync(0xffffffffu, s, o);
    if (lane == 0) (isz ? d_sz : d_se)[r] = s;
}

// ---------------------------------------------------------------- L2/L3
__global__ void __launch_bounds__(256) vq_zero() {
    int i = blockIdx.x * 256 + threadIdx.x;
    if (i < NE) d_counts[i] = 0;
}
__global__ void __launch_bounds__(256) vq_aux() {
    if (blockIdx.x == 0 && threadIdx.x == 0) d_nflag = 0;
}

// ---------------------------------------------------------------- L4: main
static __device__ __forceinline__ void load_b(uint32_t sb, int ch, int buf) {
    int tid = threadIdx.x;
    size_t k0 = (size_t)ch * BN;
    uint32_t bh = sb + OFF_B + (uint32_t)buf * 16384u;
    #pragma unroll
    for (int p = 0; p < 2; p++) {
        int l = tid + p * NTHR;
        int row = l >> 3, seg = l & 7;
        uint32_t sw = swz((uint32_t)(row * 128 + seg * 16));
        size_t g = ((k0 + row) * ED + seg * 8) * 2;
        CP_ASYNC16(bh + sw, (const char*)d_eh + g);
    }
}

__global__ void __launch_bounds__(NTHR, 1) vq_main() {
    extern __shared__ char smem[];
    uint32_t sb = smem_u32(smem);
    const int tid = threadIdx.x;
    const int w = tid >> 5, lid = tid & 31;
    const int rowgrp = w & 7;
    const int nhalf = w >> 3;
    const int m0 = blockIdx.x * BM;

    #pragma unroll
    for (int p = 0; p < 2; p++) {
        int l = tid + p * NTHR;
        int row = l >> 3, seg = l & 7;
        uint32_t sw = swz((uint32_t)(row * 128 + seg * 16));
        size_t g = (((size_t)(m0 + row)) * ED + seg * 8) * 2;
        *(uint4*)(smem + OFF_A + sw)         = *(const uint4*)((const char*)d_zh + g);
        *(uint4*)(smem + OFF_A + 16384 + sw) = *(const uint4*)((const char*)d_zl + g);
    }
    float* ses = (float*)(smem + OFF_SES);
    for (int i = tid; i < NE; i += NTHR) ses[i] = d_se[i];
    __syncthreads();

    uint32_t ah[4][4], al[4][4];
    {
        int arow = rowgrp * 16 + (lid & 7) + ((lid >> 3) & 1) * 8;
        #pragma unroll
        for (int ks = 0; ks < 4; ks++) {
            uint32_t off = swz((uint32_t)(arow * 128 + ks * 32 + (lid >> 4) * 16));
            ldsm4(ah[ks][0], ah[ks][1], ah[ks][2], ah[ks][3], sb + OFF_A + off);
            ldsm4(al[ks][0], al[ks][1], al[ks][2], al[ks][3], sb + OFF_A + 16384u + off);
        }
    }

    float v00 = 3.4e38f, v01 = 3.4e38f, v10 = 3.4e38f, v11 = 3.4e38f;
    int   i00 = 0x7fffffff, i01 = 0x7fffffff, i10 = 0x7fffffff, i11 = 0x7fffffff;

    load_b(sb, 0, 0);
    CP_COMMIT();

    const int brow_l = (lid & 7) + ((lid >> 3) & 1) * 8;
    const int boff_l = (lid >> 4) * 16;

    for (int ch = 0; ch < NCH; ch++) {
        if (ch + 1 < NCH) { load_b(sb, ch + 1, (ch + 1) & 1); CP_COMMIT(); }
        if (ch + 1 < NCH) CP_WAIT(1); else CP_WAIT(0);
        __syncthreads();

        uint32_t bbase = sb + OFF_B + (uint32_t)((ch & 1) * 16384);

        #pragma unroll
        for (int nt2 = 0; nt2 < 4; nt2++) {
            int codebase = nhalf * 64 + nt2 * 16;
            float aE[4] = {0.f, 0.f, 0.f, 0.f};
            float aO[4] = {0.f, 0.f, 0.f, 0.f};
            #pragma unroll
            for (int ks = 0; ks < 4; ks++) {
                uint32_t sa = swz((uint32_t)((codebase + brow_l) * 128 + ks * 32 + boff_l));
                uint32_t h0, h1, h2, h3;
                ldsm4(h0, h1, h2, h3, bbase + sa);
                mma_f16(aE, ah[ks], h0, h2);
                mma_f16(aO, ah[ks], h1, h3);
                mma_f16(aE, al[ks], h0, h2);
                mma_f16(aO, al[ks], h1, h3);
            }
            int cE = codebase + 2 * (lid & 3);
            float2 sE = *(const float2*)&ses[ch * BN + cE];
            float2 sO = *(const float2*)&ses[ch * BN + cE + 8];
            int kg = ch * BN + cE;
            float dv;
            dv = __fadd_rn(aE[0], sE.x); UPD2(v00, i00, v01, i01, dv, kg);
            dv = __fadd_rn(aE[1], sE.y); UPD2(v00, i00, v01, i01, dv, kg + 1);
            dv = __fadd_rn(aO[0], sO.x); UPD2(v00, i00, v01, i01, dv, kg + 8);
            dv = __fadd_rn(aO[1], sO.y); UPD2(v00, i00, v01, i01, dv, kg + 9);
            dv = __fadd_rn(aE[2], sE.x); UPD2(v10, i10, v11, i11, dv, kg);
            dv = __fadd_rn(aE[3], sE.y); UPD2(v10, i10, v11, i11, dv, kg + 1);
            dv = __fadd_rn(aO[2], sO.x); UPD2(v10, i10, v11, i11, dv, kg + 8);
            dv = __fadd_rn(aO[3], sO.y); UPD2(v10, i10, v11, i11, dv, kg + 9);
        }
        __syncthreads();
    }

    #pragma unroll
    for (int off = 2; off >= 1; off >>= 1) {
        float w0 = __shfl_down_sync(0xffffffffu, v00, off);
        int   j0 = __shfl_down_sync(0xffffffffu, i00, off);
        float w1 = __shfl_down_sync(0xffffffffu, v01, off);
        int   j1 = __shfl_down_sync(0xffffffffu, i01, off);
        MERGE2(v00, i00, v01, i01, w0, j0, w1, j1);
        w0 = __shfl_down_sync(0xffffffffu, v10, off);
        j0 = __shfl_down_sync(0xffffffffu, i10, off);
        w1 = __shfl_down_sync(0xffffffffu, v11, off);
        j1 = __shfl_down_sync(0xffffffffu, i11, off);
        MERGE2(v10, i10, v11, i11, w0, j0, w1, j1);
    }
    if ((lid & 3) == 0) {
        int t0 = m0 + rowgrp * 16 + (lid >> 2);
        ((float2*)d_c2v)[(size_t)t0 * 2 + nhalf]       = make_float2(v00, v01);
        ((int2*)  d_c2i)[(size_t)t0 * 2 + nhalf]       = make_int2(i00, i01);
        ((float2*)d_c2v)[(size_t)(t0 + 8) * 2 + nhalf] = make_float2(v10, v11);
        ((int2*)  d_c2i)[(size_t)(t0 + 8) * 2 + nhalf] = make_int2(i10, i11);
    }
}

// ---------------------------------------------------------------- L5: pick
// Certify wide-gap tokens; exactly rescore <=4 in-window candidates inline;
// flag for full scan only when a half's 2nd-best is in-window (containment risk).
__global__ void __launch_bounds__(256) vq_pick(const float* __restrict__ z,
                                               const float* __restrict__ cb) {
    int t = blockIdx.x * 256 + threadIdx.x;
    float2 a  = ((const float2*)d_c2v)[(size_t)t * 2];
    float2 b  = ((const float2*)d_c2v)[(size_t)t * 2 + 1];
    int2   ai = ((const int2*)  d_c2i)[(size_t)t * 2];
    int2   bi = ((const int2*)  d_c2i)[(size_t)t * 2 + 1];

    // global best among 4 (halves are disjoint code sets)
    float v0 = a.x; int i0 = ai.x;
    if (b.x < v0 || (b.x == v0 && bi.x < i0)) { v0 = b.x; i0 = bi.x; }
    float thr = v0 + EPSW;

    bool deep = (a.y <= thr) || (b.y <= thr);
    int nin = (a.x <= thr) + (a.y <= thr) + (b.x <= thr) + (b.y <= thr);

    int winner = i0;
    if (!deep && nin > 1) {
        // exact rescore of in-window candidates (reference chain)
        float zr[64];
        const float4* z4 = (const float4*)(z + (size_t)t * ED);
        #pragma unroll
        for (int q = 0; q < 16; q++) {
            float4 v = z4[q];
            zr[q*4] = v.x; zr[q*4+1] = v.y; zr[q*4+2] = v.z; zr[q*4+3] = v.w;
        }
        float szt = d_sz[t];
        float bv = 3.4e38f; int bk = 0x7fffffff;
        float cv[4] = {a.x, a.y, b.x, b.y};
        int   ck[4] = {ai.x, ai.y, bi.x, bi.y};
        #pragma unroll
        for (int j = 0; j < 4; j++) {
            if (cv[j] <= thr) {
                float dv = exact_d(zr, cb, szt, ck[j]);
                if (dv < bv || (dv == bv && ck[j] < bk)) { bv = dv; bk = ck[j]; }
            }
        }
        winner = bk;
    }
    d_win[t] = winner;
    if (deep) {
        int p = atomicAdd(&d_nflag, 1);
        d_flag[p] = t;
    }
}

// ---------------------------------------------------------------- L6: exact
// Warp per deep-flagged token; full exact scan, grid-stride over the list.
__global__ void __launch_bounds__(256) vq_exact(const float* __restrict__ z,
                                                const float* __restrict__ cb) {
    __shared__ float s_z[8][64];
    int nf = d_nflag;
    int lw = threadIdx.x >> 5, l = threadIdx.x & 31;
    int nwarps = gridDim.x * 8;

    for (int i = blockIdx.x * 8 + lw; i < nf; i += nwarps) {
        int t = d_flag[i];
        s_z[lw][l]      = z[(size_t)t * ED + l];
        s_z[lw][l + 32] = z[(size_t)t * ED + 32 + l];
        __syncwarp();
        float szt = d_sz[t];
        const float* zr = s_z[lw];

        float bv = 3.4e38f; int bi = 0x7fffffff;
        for (int c = l; c < NE; c += 32) {
            float dv = exact_d(zr, cb, szt, c);
            if (dv < bv) { bv = dv; bi = c; }   // increasing c per lane
        }
        #pragma unroll
        for (int o = 16; o; o >>= 1) {
            float ov = __shfl_xor_sync(0xffffffffu, bv, o);
            int   oi = __shfl_xor_sync(0xffffffffu, bi, o);
            if (ov < bv || (ov == bv && oi < bi)) { bv = ov; bi = oi; }
        }
        if (l == 0) d_win[t] = bi;
        __syncwarp();
    }
}

// ---------------------------------------------------------------- L7: write
__global__ void __launch_bounds__(256) vq_write(const float* __restrict__ z,
                                                const float* __restrict__ cb,
                                                float* __restrict__ out) {
    int t = (blockIdx.x * 256 + threadIdx.x) >> 5;
    int l = threadIdx.x & 31;
    int winner = d_win[t];

    if (l == 0) {
        out[OUT_IDX_OFF + t] = (float)winner;
        atomicAdd(&d_counts[winner], 1);
    }
    float lacc = 0.f;
    #pragma unroll
    for (int p = 0; p < 2; p++) {
        int d = l + p * 32;
        float zq = cb[(size_t)winner * ED + d];
        float zv = z[(size_t)t * ED + d];
        float tt = __fsub_rn(zq, zv);
        out[OUT_ZQ_OFF + (size_t)t * ED + d] = __fadd_rn(zv, tt);
        lacc = __fmaf_rn(tt, tt, lacc);
    }
    #pragma unroll
    for (int o = 16; o; o >>= 1) lacc += __shfl_xor_sync(0xffffffffu, lacc, o);
    if (l == 0) d_losstok[t] = lacc;
}

// ---------------------------------------------------------------- L8: finalize
__global__ void __launch_bounds__(1024) vq_finalize(float* __restrict__ out) {
    __shared__ double sh[1024];
    int tid = threadIdx.x;
    double s = 0.0;
    for (int i = tid; i < N_TOK; i += 1024) s += (double)d_losstok[i];
    sh[tid] = s;
    __syncthreads();
    #pragma unroll
    for (int st = 512; st > 0; st >>= 1) {
        if (tid < st) sh[tid] += sh[tid + st];
        __syncthreads();
    }
    if (tid == 0)
        out[0] = (float)(1.25 * sh[0] / (double)((size_t)N_TOK * ED));
    __syncthreads();

    double h = 0.0;
    for (int i = tid; i < NE; i += 1024) {
        float em = (float)d_counts[i] / (float)N_TOK;
        h += (double)(em * logf(em + 1e-10f));
    }
    sh[tid] = h;
    __syncthreads();
    #pragma unroll
    for (int st = 512; st > 0; st >>= 1) {
        if (tid < st) sh[tid] += sh[tid + st];
        __syncthreads();
    }
    if (tid == 0)
        out[OUT_PERP_OFF] = expf(-(float)sh[0]);
}

// ---------------------------------------------------------------- launch
extern "C" void kernel_launch(void* const* d_in, const int* in_sizes, int n_in,
                              void* d_out, int out_size) {
    const float* z  = (const float*)d_in[0];
    const float* cb = (const float*)d_in[1];
    float* out = (float*)d_out;

    cudaFuncSetAttribute(vq_main, cudaFuncAttributeMaxDynamicSharedMemorySize, SMEM_MAIN);

    vq_prep<<<2560, 256>>>(z, cb);            // L1
    vq_zero<<<16, 256>>>();                   // L2
    vq_aux<<<1, 256>>>();                     // L3
    vq_main<<<NBLK, NTHR, SMEM_MAIN>>>();     // L4
    vq_pick<<<N_TOK / 256, 256>>>(z, cb);     // L5
    vq_exact<<<128, 256>>>(z, cb);            // L6
    vq_write<<<N_TOK / 8, 256>>>(z, cb, out); // L7
    vq_finalize<<<1, 1024>>>(out);            // L8
}

// round 9
// speedup vs baseline: 1.7420x; 1.7420x over previous
#include <cuda_runtime.h>
#include <cuda_fp16.h>
#include <math.h>
#include <stdint.h>

// ---------------------------------------------------------------- constants
#define N_TOK 16384
#define NE    4096
#define ED    64
#define BM    128          // tokens per CTA
#define BN    128          // codes per chunk
#define NCH   (NE/BN)      // 32
#define NBLK  (N_TOK/BM)   // 128
#define NTHR  512
#define EPSW  4.0e-5f      // ref reorder slack (~1.5e-5) + 2x fp16-drop bound + margin

#define OUT_ZQ_OFF   1
#define OUT_IDX_OFF  (1 + (size_t)N_TOK*ED)
#define OUT_PERP_OFF (OUT_IDX_OFF + N_TOK)

// SMEM layout of vq_main
#define OFF_A    0                 // zh 16K + zl 16K
#define OFF_B    32768             // 2 bufs x 16K (eh only)
#define OFF_SES  65536             // 16K fp32 ||e||^2
#define SMEM_MAIN (OFF_SES + NE*4) // 81920

// ---------------------------------------------------------------- scratch
__device__ __align__(16) __half d_zh[N_TOK*ED];   // hi(-2z)
__device__ __align__(16) __half d_zl[N_TOK*ED];   // lo(-2z)
__device__ __align__(16) __half d_eh[NE*ED];      // hi(e)
__device__ float d_sz[N_TOK];
__device__ float d_se[NE];
__device__ int   d_counts[NE];
__device__ float d_losstok[N_TOK];
__device__ __align__(16) float d_bd[(size_t)N_TOK*16];   // 16 candidates/token
__device__ __align__(16) int   d_bi[(size_t)N_TOK*16];
__device__ int   d_win[N_TOK];
__device__ unsigned long long d_best[N_TOK];
__device__ unsigned d_pairs[(size_t)N_TOK*16];
__device__ int   d_deep[N_TOK];
__device__ int   d_npairs;
__device__ int   d_ndeep;

// ---------------------------------------------------------------- utils
static __device__ __forceinline__ uint32_t smem_u32(const void* p) {
    uint32_t a;
    asm("{ .reg .u64 t; cvta.to.shared.u64 t, %1; cvt.u32.u64 %0, t; }"
        : "=r"(a) : "l"(p));
    return a;
}
static __device__ __forceinline__ uint32_t swz(uint32_t o) { return o ^ ((o >> 3) & 0x70); }

static __device__ __forceinline__ void ldsm4(uint32_t& r0, uint32_t& r1,
                                             uint32_t& r2, uint32_t& r3, uint32_t a) {
    asm volatile("ldmatrix.sync.aligned.m8n8.x4.shared.b16 {%0,%1,%2,%3}, [%4];"
                 : "=r"(r0), "=r"(r1), "=r"(r2), "=r"(r3) : "r"(a));
}
static __device__ __forceinline__ void mma_f16(float c[4], const uint32_t a[4],
                                               uint32_t b0, uint32_t b1) {
    asm volatile("mma.sync.aligned.m16n8k16.row.col.f32.f16.f16.f32 "
                 "{%0,%1,%2,%3}, {%4,%5,%6,%7}, {%8,%9}, {%0,%1,%2,%3};"
                 : "+f"(c[0]), "+f"(c[1]), "+f"(c[2]), "+f"(c[3])
                 : "r"(a[0]), "r"(a[1]), "r"(a[2]), "r"(a[3]), "r"(b0), "r"(b1));
}
#define CP_ASYNC16(s, g) \
    asm volatile("cp.async.cg.shared.global [%0], [%1], 16;" :: "r"(s), "l"(g))
#define CP_COMMIT() asm volatile("cp.async.commit_group;" ::: "memory")
#define CP_WAIT(n)  asm volatile("cp.async.wait_group %0;" :: "n"(n) : "memory")

#define UPD2(v0, i0, v1, i1, dv, kk) do { \
    bool _p0 = (dv) < (v0); \
    bool _p1 = (dv) < (v1); \
    (v1) = _p0 ? (v0) : (_p1 ? (dv) : (v1)); \
    (i1) = _p0 ? (i0) : (_p1 ? (kk) : (i1)); \
    (v0) = _p0 ? (dv) : (v0); \
    (i0) = _p0 ? (kk) : (i0); \
} while (0)

// exact reference-chain distance; sequential FMA d=0..63 (bit-matched in R1)
static __device__ __forceinline__ float exact_chain(const float* __restrict__ z,
                                                    const float* __restrict__ cb,
                                                    int t, int k) {
    const float4* z4 = (const float4*)(z + (size_t)t * ED);
    const float4* c4 = (const float4*)(cb + (size_t)k * ED);
    float dot = 0.f;
    #pragma unroll
    for (int q = 0; q < 16; q++) {
        float4 a = z4[q], b = c4[q];
        dot = __fmaf_rn(a.x, b.x, dot);
        dot = __fmaf_rn(a.y, b.y, dot);
        dot = __fmaf_rn(a.z, b.z, dot);
        dot = __fmaf_rn(a.w, b.w, dot);
    }
    return __fmaf_rn(-2.0f, dot, __fadd_rn(d_sz[t], d_se[k]));
}
static __device__ __forceinline__ unsigned long long packdi(float d, int k) {
    return ((unsigned long long)__float_as_uint(d) << 32) | (unsigned)k;
}

// ---------------------------------------------------------------- L1: prep
__global__ void __launch_bounds__(256) vq_prep(const float* __restrict__ z,
                                               const float* __restrict__ cb) {
    int b = blockIdx.x, tid = threadIdx.x;
    int w = tid >> 5, lane = tid & 31;
    int row = b * 8 + w;
    bool isz = row < N_TOK;
    const float* src = isz ? z : cb;
    int r = isz ? row : row - N_TOK;

    float2 v = *(const float2*)&src[(size_t)r * ED + lane * 2];
    float sc = isz ? -2.0f : 1.0f;
    float m0 = sc * v.x, m1 = sc * v.y;
    __half h0 = __float2half_rn(m0), h1 = __float2half_rn(m1);
    __half2 hh; hh.x = h0; hh.y = h1;
    if (isz) {
        float l0 = m0 - __half2float(h0), l1 = m1 - __half2float(h1);
        __half2 ll; ll.x = __float2half_rn(l0); ll.y = __float2half_rn(l1);
        ((__half2*)d_zh)[(size_t)r * 32 + lane] = hh;
        ((__half2*)d_zl)[(size_t)r * 32 + lane] = ll;
    } else {
        ((__half2*)d_eh)[(size_t)r * 32 + lane] = hh;
    }

    float s = __fmaf_rn(v.x, v.x, v.y * v.y);
    #pragma unroll
    for (int o = 16; o; o >>= 1) s += __shfl_xor_sync(0xffffffffu, s, o);
    if (lane == 0) (isz ? d_sz : d_se)[r] = s;
}

// ---------------------------------------------------------------- L2/L3
__global__ void __launch_bounds__(256) vq_zero() {
    int i = blockIdx.x * 256 + threadIdx.x;
    if (i < NE) d_counts[i] = 0;
}
__global__ void __launch_bounds__(256) vq_aux() {
    if (blockIdx.x == 0 && threadIdx.x == 0) { d_npairs = 0; d_ndeep = 0; }
}

// ---------------------------------------------------------------- L4: main
static __device__ __forceinline__ void load_b(uint32_t sb, int ch, int buf) {
    int tid = threadIdx.x;
    size_t k0 = (size_t)ch * BN;
    uint32_t bh = sb + OFF_B + (uint32_t)buf * 16384u;
    #pragma unroll
    for (int p = 0; p < 2; p++) {
        int l = tid + p * NTHR;
        int row = l >> 3, seg = l & 7;
        uint32_t sw = swz((uint32_t)(row * 128 + seg * 16));
        size_t g = ((k0 + row) * ED + seg * 8) * 2;
        CP_ASYNC16(bh + sw, (const char*)d_eh + g);
    }
}

__global__ void __launch_bounds__(NTHR, 1) vq_main() {
    extern __shared__ char smem[];
    uint32_t sb = smem_u32(smem);
    const int tid = threadIdx.x;
    const int w = tid >> 5, lid = tid & 31;
    const int rowgrp = w & 7;
    const int nhalf = w >> 3;
    const int m0 = blockIdx.x * BM;

    #pragma unroll
    for (int p = 0; p < 2; p++) {
        int l = tid + p * NTHR;
        int row = l >> 3, seg = l & 7;
        uint32_t sw = swz((uint32_t)(row * 128 + seg * 16));
        size_t g = (((size_t)(m0 + row)) * ED + seg * 8) * 2;
        *(uint4*)(smem + OFF_A + sw)         = *(const uint4*)((const char*)d_zh + g);
        *(uint4*)(smem + OFF_A + 16384 + sw) = *(const uint4*)((const char*)d_zl + g);
    }
    float* ses = (float*)(smem + OFF_SES);
    for (int i = tid; i < NE; i += NTHR) ses[i] = d_se[i];
    __syncthreads();

    uint32_t ah[4][4], al[4][4];
    {
        int arow = rowgrp * 16 + (lid & 7) + ((lid >> 3) & 1) * 8;
        #pragma unroll
        for (int ks = 0; ks < 4; ks++) {
            uint32_t off = swz((uint32_t)(arow * 128 + ks * 32 + (lid >> 4) * 16));
            ldsm4(ah[ks][0], ah[ks][1], ah[ks][2], ah[ks][3], sb + OFF_A + off);
            ldsm4(al[ks][0], al[ks][1], al[ks][2], al[ks][3], sb + OFF_A + 16384u + off);
        }
    }

    float v00 = 3.4e38f, v01 = 3.4e38f, v10 = 3.4e38f, v11 = 3.4e38f;
    int   i00 = 0x7fffffff, i01 = 0x7fffffff, i10 = 0x7fffffff, i11 = 0x7fffffff;

    load_b(sb, 0, 0);
    CP_COMMIT();

    const int brow_l = (lid & 7) + ((lid >> 3) & 1) * 8;
    const int boff_l = (lid >> 4) * 16;

    for (int ch = 0; ch < NCH; ch++) {
        if (ch + 1 < NCH) { load_b(sb, ch + 1, (ch + 1) & 1); CP_COMMIT(); }
        if (ch + 1 < NCH) CP_WAIT(1); else CP_WAIT(0);
        __syncthreads();

        uint32_t bbase = sb + OFF_B + (uint32_t)((ch & 1) * 16384);

        #pragma unroll
        for (int nt2 = 0; nt2 < 4; nt2++) {
            int codebase = nhalf * 64 + nt2 * 16;
            float aE[4] = {0.f, 0.f, 0.f, 0.f};
            float aO[4] = {0.f, 0.f, 0.f, 0.f};
            #pragma unroll
            for (int ks = 0; ks < 4; ks++) {
                uint32_t sa = swz((uint32_t)((codebase + brow_l) * 128 + ks * 32 + boff_l));
                uint32_t h0, h1, h2, h3;
                ldsm4(h0, h1, h2, h3, bbase + sa);
                mma_f16(aE, ah[ks], h0, h2);
                mma_f16(aO, ah[ks], h1, h3);
                mma_f16(aE, al[ks], h0, h2);
                mma_f16(aO, al[ks], h1, h3);
            }
            int cE = codebase + 2 * (lid & 3);
            float2 sE = *(const float2*)&ses[ch * BN + cE];
            float2 sO = *(const float2*)&ses[ch * BN + cE + 8];
            int kg = ch * BN + cE;
            float dv;
            dv = __fadd_rn(aE[0], sE.x); UPD2(v00, i00, v01, i01, dv, kg);
            dv = __fadd_rn(aE[1], sE.y); UPD2(v00, i00, v01, i01, dv, kg + 1);
            dv = __fadd_rn(aO[0], sO.x); UPD2(v00, i00, v01, i01, dv, kg + 8);
            dv = __fadd_rn(aO[1], sO.y); UPD2(v00, i00, v01, i01, dv, kg + 9);
            dv = __fadd_rn(aE[2], sE.x); UPD2(v10, i10, v11, i11, dv, kg);
            dv = __fadd_rn(aE[3], sE.y); UPD2(v10, i10, v11, i11, dv, kg + 1);
            dv = __fadd_rn(aO[2], sO.x); UPD2(v10, i10, v11, i11, dv, kg + 8);
            dv = __fadd_rn(aO[3], sO.y); UPD2(v10, i10, v11, i11, dv, kg + 9);
        }
        __syncthreads();
    }

    // store per-thread best-2: 16 slots/token
    int t0 = m0 + rowgrp * 16 + (lid >> 2);
    int slot = nhalf * 8 + (lid & 3) * 2;
    *(float2*)(d_bd + (size_t)t0 * 16 + slot)       = make_float2(v00, v01);
    *(int2*)  (d_bi + (size_t)t0 * 16 + slot)       = make_int2(i00, i01);
    *(float2*)(d_bd + (size_t)(t0 + 8) * 16 + slot) = make_float2(v10, v11);
    *(int2*)  (d_bi + (size_t)(t0 + 8) * 16 + slot) = make_int2(i10, i11);
}

// ---------------------------------------------------------------- L5: pick
__global__ void __launch_bounds__(256) vq_pick() {
    int t = blockIdx.x * 256 + threadIdx.x;
    float bv[16]; int bx[16];
    #pragma unroll
    for (int q = 0; q < 4; q++) {
        float4 fv = *(const float4*)(d_bd + (size_t)t * 16 + q * 4);
        int4   iv = *(const int4*)  (d_bi + (size_t)t * 16 + q * 4);
        bv[q*4] = fv.x; bv[q*4+1] = fv.y; bv[q*4+2] = fv.z; bv[q*4+3] = fv.w;
        bx[q*4] = iv.x; bx[q*4+1] = iv.y; bx[q*4+2] = iv.z; bx[q*4+3] = iv.w;
    }
    float gv = bv[0]; int gi = bx[0];
    #pragma unroll
    for (int j = 1; j < 16; j++)
        if (bv[j] < gv || (bv[j] == gv && bx[j] < gi)) { gv = bv[j]; gi = bx[j]; }
    float thr = gv + EPSW;

    int cnt = 0; bool deep = false;
    #pragma unroll
    for (int j = 0; j < 16; j++) {
        bool in = bv[j] <= thr;
        cnt += in;
        if (in && (j & 1)) deep = true;   // a thread's 2nd-best in-window
    }

    if (cnt == 1 && !deep) {
        d_win[t] = gi;
    } else {
        d_win[t] = -1;
        d_best[t] = 0xFFFFFFFFFFFFFFFFULL;
        if (deep) {
            int p = atomicAdd(&d_ndeep, 1);
            d_deep[p] = t;
        } else {
            int base = atomicAdd(&d_npairs, cnt);
            int o = 0;
            #pragma unroll
            for (int j = 0; j < 16; j++)
                if (bv[j] <= thr) d_pairs[base + o++] = ((unsigned)t << 12) | (unsigned)bx[j];
        }
    }
}

// ---------------------------------------------------------------- L6: pairs
__global__ void __launch_bounds__(256) vq_pairs(const float* __restrict__ z,
                                                const float* __restrict__ cb) {
    int np = d_npairs;
    for (int i = blockIdx.x * 256 + threadIdx.x; i < np; i += gridDim.x * 256) {
        unsigned p = d_pairs[i];
        int t = (int)(p >> 12), k = (int)(p & 4095u);
        float dv = exact_chain(z, cb, t, k);
        atomicMin(&d_best[t], packdi(dv, k));
    }
}

// ---------------------------------------------------------------- L7: deep
// Each work item = (deep token, 512-row segment); grid-stride over items.
__global__ void __launch_bounds__(256) vq_deep(const float* __restrict__ z,
                                               const float* __restrict__ cb) {
    int nd = d_ndeep;
    int items = nd * 8;
    for (int it = blockIdx.x; it < items; it += gridDim.x) {
        int t = d_deep[it >> 3];
        int r0 = (it & 7) * 512 + threadIdx.x * 2;
        unsigned long long best = 0xFFFFFFFFFFFFFFFFULL;
        #pragma unroll
        for (int rr = 0; rr < 2; rr++) {
            int k = r0 + rr;
            float dv = exact_chain(z, cb, t, k);
            unsigned long long pk = packdi(dv, k);
            if (pk < best) best = pk;
        }
        atomicMin(&d_best[t], best);
    }
}

// ---------------------------------------------------------------- L8: write
__global__ void __launch_bounds__(256) vq_write(const float* __restrict__ z,
                                                const float* __restrict__ cb,
                                                float* __restrict__ out) {
    int t = (blockIdx.x * 256 + threadIdx.x) >> 5;
    int l = threadIdx.x & 31;
    int wv = d_win[t];
    int winner = (wv >= 0) ? wv : (int)(d_best[t] & 0xFFFFFFFFULL);

    if (l == 0) {
        out[OUT_IDX_OFF + t] = (float)winner;
        atomicAdd(&d_counts[winner], 1);
    }
    float lacc = 0.f;
    #pragma unroll
    for (int p = 0; p < 2; p++) {
        int d = l + p * 32;
        float zq = cb[(size_t)winner * ED + d];
        float zv = z[(size_t)t * ED + d];
        float tt = __fsub_rn(zq, zv);
        out[OUT_ZQ_OFF + (size_t)t * ED + d] = __fadd_rn(zv, tt);
        lacc = __fmaf_rn(tt, tt, lacc);
    }
    #pragma unroll
    for (int o = 16; o; o >>= 1) lacc += __shfl_xor_sync(0xffffffffu, lacc, o);
    if (l == 0) d_losstok[t] = lacc;
}

// ---------------------------------------------------------------- L9: finalize
__global__ void __launch_bounds__(1024) vq_finalize(float* __restrict__ out) {
    __shared__ double sh[1024];
    int tid = threadIdx.x;
    double s = 0.0;
    for (int i = tid; i < N_TOK; i += 1024) s += (double)d_losstok[i];
    sh[tid] = s;
    __syncthreads();
    #pragma unroll
    for (int st = 512; st > 0; st >>= 1) {
        if (tid < st) sh[tid] += sh[tid + st];
        __syncthreads();
    }
    if (tid == 0)
        out[0] = (float)(1.25 * sh[0] / (double)((size_t)N_TOK * ED));
    __syncthreads();

    double h = 0.0;
    for (int i = tid; i < NE; i += 1024) {
        float em = (float)d_counts[i] / (float)N_TOK;
        h += (double)(em * logf(em + 1e-10f));
    }
    sh[tid] = h;
    __syncthreads();
    #pragma unroll
    for (int st = 512; st > 0; st >>= 1) {
        if (tid < st) sh[tid] += sh[tid + st];
        __syncthreads();
    }
    if (tid == 0)
        out[OUT_PERP_OFF] = expf(-(float)sh[0]);
}

// ---------------------------------------------------------------- launch
extern "C" void kernel_launch(void* const* d_in, const int* in_sizes, int n_in,
                              void* d_out, int out_size) {
    const float* z  = (const float*)d_in[0];
    const float* cb = (const float*)d_in[1];
    float* out = (float*)d_out;

    cudaFuncSetAttribute(vq_main, cudaFuncAttributeMaxDynamicSharedMemorySize, SMEM_MAIN);

    vq_prep<<<2560, 256>>>(z, cb);            // L1
    vq_zero<<<16, 256>>>();                   // L2
    vq_aux<<<1, 256>>>();                     // L3
    vq_main<<<NBLK, NTHR, SMEM_MAIN>>>();     // L4
    vq_pick<<<N_TOK / 256, 256>>>();          // L5
    vq_pairs<<<64, 256>>>(z, cb);             // L6
    vq_deep<<<64, 256>>>(z, cb);              // L7
    vq_write<<<N_TOK / 8, 256>>>(z, cb, out); // L8
    vq_finalize<<<1, 1024>>>(out);            // L9
}